// round 3
// baseline (speedup 1.0000x reference)
#include <cuda_runtime.h>
#include <cuda_bf16.h>

// Problem constants (match reference)
#define NU 50000
#define NI 25000
#define FU 128
#define FI 64
#define HD 128
#define OD 64
#define EB  400000
#define EBB 400000
#define EF  200000

// ---------------- scratch (static device memory; no allocation allowed) ----
__device__ float g_hu  [NU * HD];
__device__ float g_hi  [NI * HD];
__device__ float g_hu2 [NU * HD];
__device__ float g_hi2 [NI * HD];
__device__ float g_y   [NU * HD];   // transformed-src scratch (max size)
__device__ float g_accU1[NU * HD];
__device__ float g_accU2[NU * HD];
__device__ float g_accI [NI * HD];
__device__ int   g_cntB [NI];
__device__ int   g_cntBB[NU];
__device__ int   g_cntF [NU];

// ---------------- small utility kernels ------------------------------------
__global__ void zero_f_kernel(float* __restrict__ p, int n) {
    int t = blockIdx.x * blockDim.x + threadIdx.x;
    if (t < n) p[t] = 0.f;
}
__global__ void zero_i_kernel(int* __restrict__ p, int n) {
    int t = blockIdx.x * blockDim.x + threadIdx.x;
    if (t < n) p[t] = 0;
}
__global__ void count_deg_kernel(const int* __restrict__ dst, int* __restrict__ cnt, int E) {
    int t = blockIdx.x * blockDim.x + threadIdx.x;
    if (t < E) atomicAdd(&cnt[dst[t]], 1);
}

// Scatter: acc[dst[e], :] += y[src[e], :]   (vectorized x4, atomics)
__global__ void scatter_add4_kernel(const float* __restrict__ y,
                                    const int* __restrict__ src,
                                    const int* __restrict__ dst,
                                    float* __restrict__ acc,
                                    int E, int N) {
    const int nq = N >> 2;                     // float4 groups per row
    const int total = E * nq;                  // fits in int for our sizes
    int t = blockIdx.x * blockDim.x + threadIdx.x;
    if (t >= total) return;
    int e = t / nq;
    int c = (t - e * nq) << 2;
    int s = src[e], d = dst[e];
    float4 v = *reinterpret_cast<const float4*>(&y[(size_t)s * N + c]);
    float* a = &acc[(size_t)d * N + c];
    atomicAdd(a + 0, v.x);
    atomicAdd(a + 1, v.y);
    atomicAdd(a + 2, v.z);
    atomicAdd(a + 3, v.w);
}

// ---------------- GEMM with fused SAGE epilogue -----------------------------
// C[m,n] = scale*( A[m,:]@(W1+W2)[:,n] + b1[n] + b2[n]
//                  + acc1[m,n]/max(cnt1[m],1) + acc2[m,n]/max(cnt2[m],1) )
// optional relu.  Null pointers disable the corresponding term.
// Requires: K % 32 == 0, N % 64 == 0.
__global__ __launch_bounds__(256)
void gemm_ep_kernel(const float* __restrict__ A,
                    const float* __restrict__ W1,
                    const float* __restrict__ W2,
                    const float* __restrict__ b1,
                    const float* __restrict__ b2,
                    const float* __restrict__ acc1,
                    const int*   __restrict__ cnt1,
                    const float* __restrict__ acc2,
                    const int*   __restrict__ cnt2,
                    float* __restrict__ C,
                    int M, int N, int K, float scale, int relu)
{
    constexpr int BM = 128, BN = 64, BK = 32, TM = 8, TN = 4;
    __shared__ float As[BK][BM + 4];   // +4 pad: spreads store banks
    __shared__ float Bs[BK][BN];

    const int bm  = blockIdx.y * BM;
    const int bn  = blockIdx.x * BN;
    const int tid = threadIdx.x;       // 0..255
    const int tx  = tid & 15;          // N direction (16)
    const int ty  = tid >> 4;          // M direction (16)

    float r[TM][TN] = {};

    for (int k0 = 0; k0 < K; k0 += BK) {
        // --- A tile: BM x BK (128x32) = 1024 float4, 4 per thread ---
        #pragma unroll
        for (int it = 0; it < 4; ++it) {
            int idx = tid + it * 256;          // 0..1023
            int row = idx >> 3;                // /(BK/4)
            int kq  = idx & 7;
            float4 v = make_float4(0.f, 0.f, 0.f, 0.f);
            int gm = bm + row;
            if (gm < M)
                v = *reinterpret_cast<const float4*>(&A[(size_t)gm * K + k0 + (kq << 2)]);
            As[(kq << 2) + 0][row] = v.x;
            As[(kq << 2) + 1][row] = v.y;
            As[(kq << 2) + 2][row] = v.z;
            As[(kq << 2) + 3][row] = v.w;
        }
        // --- B tile: BK x BN (32x64) = 512 float4, 2 per thread ---
        #pragma unroll
        for (int it = 0; it < 2; ++it) {
            int idx = tid + it * 256;          // 0..511
            int row = idx >> 4;                // /(BN/4)
            int cq  = idx & 15;
            size_t off = (size_t)(k0 + row) * N + bn + (cq << 2);
            float4 v = *reinterpret_cast<const float4*>(&W1[off]);
            if (W2) {
                float4 v2 = *reinterpret_cast<const float4*>(&W2[off]);
                v.x += v2.x; v.y += v2.y; v.z += v2.z; v.w += v2.w;
            }
            *reinterpret_cast<float4*>(&Bs[row][cq << 2]) = v;
        }
        __syncthreads();

        #pragma unroll
        for (int kk = 0; kk < BK; ++kk) {
            float a[TM];
            #pragma unroll
            for (int i = 0; i < TM; ++i) a[i] = As[kk][ty * TM + i];
            float4 bv = *reinterpret_cast<const float4*>(&Bs[kk][tx * TN]);
            float b[TN] = {bv.x, bv.y, bv.z, bv.w};
            #pragma unroll
            for (int i = 0; i < TM; ++i)
                #pragma unroll
                for (int j = 0; j < TN; ++j)
                    r[i][j] = fmaf(a[i], b[j], r[i][j]);
        }
        __syncthreads();
    }

    // --- epilogue ---
    #pragma unroll
    for (int i = 0; i < TM; ++i) {
        int m = bm + ty * TM + i;
        if (m >= M) break;                    // thread rows are contiguous
        float inv1 = 0.f, inv2 = 0.f;
        if (acc1) { int c = cnt1[m]; inv1 = 1.f / (float)(c > 0 ? c : 1); }
        if (acc2) { int c = cnt2[m]; inv2 = 1.f / (float)(c > 0 ? c : 1); }
        #pragma unroll
        for (int j = 0; j < TN; ++j) {
            int n = bn + tx * TN + j;
            float v = r[i][j];
            if (b1)   v += b1[n];
            if (b2)   v += b2[n];
            if (acc1) v += acc1[(size_t)m * N + n] * inv1;
            if (acc2) v += acc2[(size_t)m * N + n] * inv2;
            v *= scale;
            if (relu) v = fmaxf(v, 0.f);
            C[(size_t)m * N + n] = v;
        }
    }
}

// ---------------- host side --------------------------------------------------
static inline void launch_zero_f(float* p, int n) {
    zero_f_kernel<<<(n + 255) / 256, 256>>>(p, n);
}
static inline void launch_zero_i(int* p, int n) {
    zero_i_kernel<<<(n + 255) / 256, 256>>>(p, n);
}
static inline void launch_gemm(const float* A, const float* W1, const float* W2,
                               const float* b1, const float* b2,
                               const float* acc1, const int* cnt1,
                               const float* acc2, const int* cnt2,
                               float* C, int M, int N, int K,
                               float scale, int relu) {
    dim3 grid((N + 63) / 64, (M + 127) / 128);
    gemm_ep_kernel<<<grid, 256>>>(A, W1, W2, b1, b2, acc1, cnt1, acc2, cnt2,
                                  C, M, N, K, scale, relu);
}
static inline void launch_scatter(const float* y, const int* src, const int* dst,
                                  float* acc, int E, int N) {
    int total = E * (N >> 2);
    scatter_add4_kernel<<<(total + 255) / 256, 256>>>(y, src, dst, acc, E, N);
}
static inline void launch_count(const int* dst, int* cnt, int E) {
    count_deg_kernel<<<(E + 255) / 256, 256>>>(dst, cnt, E);
}

extern "C" void kernel_launch(void* const* d_in, const int* in_sizes, int n_in,
                              void* d_out, int out_size) {
    (void)in_sizes; (void)n_in;
    const float* x_user      = (const float*)d_in[0];
    const float* x_item      = (const float*)d_in[1];
    const int*   src_buys    = (const int*)d_in[2];
    const int*   dst_buys    = (const int*)d_in[3];
    const int*   src_bought  = (const int*)d_in[4];
    const int*   dst_bought  = (const int*)d_in[5];
    const int*   src_follows = (const int*)d_in[6];
    const int*   dst_follows = (const int*)d_in[7];
    const float* lin_u_W = (const float*)d_in[8];
    const float* lin_u_b = (const float*)d_in[9];
    const float* lin_i_W = (const float*)d_in[10];
    const float* lin_i_b = (const float*)d_in[11];
    const float* c1_buys_Wl    = (const float*)d_in[12];
    const float* c1_buys_bl    = (const float*)d_in[13];
    const float* c1_buys_Wr    = (const float*)d_in[14];
    const float* c1_bought_Wl  = (const float*)d_in[15];
    const float* c1_bought_bl  = (const float*)d_in[16];
    const float* c1_bought_Wr  = (const float*)d_in[17];
    const float* c1_follows_Wl = (const float*)d_in[18];
    const float* c1_follows_bl = (const float*)d_in[19];
    const float* c1_follows_Wr = (const float*)d_in[20];
    const float* c2_buys_Wl    = (const float*)d_in[21];
    const float* c2_buys_bl    = (const float*)d_in[22];
    const float* c2_buys_Wr    = (const float*)d_in[23];
    const float* c2_bought_Wl  = (const float*)d_in[24];
    const float* c2_bought_bl  = (const float*)d_in[25];
    const float* c2_bought_Wr  = (const float*)d_in[26];
    const float* c2_follows_Wl = (const float*)d_in[27];
    const float* c2_follows_bl = (const float*)d_in[28];
    const float* c2_follows_Wr = (const float*)d_in[29];

    void *p;
    float *hu, *hi, *hu2, *hi2, *y, *accU1, *accU2, *accI;
    int *cntB, *cntBB, *cntF;
    cudaGetSymbolAddress(&p, g_hu);    hu    = (float*)p;
    cudaGetSymbolAddress(&p, g_hi);    hi    = (float*)p;
    cudaGetSymbolAddress(&p, g_hu2);   hu2   = (float*)p;
    cudaGetSymbolAddress(&p, g_hi2);   hi2   = (float*)p;
    cudaGetSymbolAddress(&p, g_y);     y     = (float*)p;
    cudaGetSymbolAddress(&p, g_accU1); accU1 = (float*)p;
    cudaGetSymbolAddress(&p, g_accU2); accU2 = (float*)p;
    cudaGetSymbolAddress(&p, g_accI);  accI  = (float*)p;
    cudaGetSymbolAddress(&p, g_cntB);  cntB  = (int*)p;
    cudaGetSymbolAddress(&p, g_cntBB); cntBB = (int*)p;
    cudaGetSymbolAddress(&p, g_cntF);  cntF  = (int*)p;

    float* out_u = (float*)d_out;             // [NU, OD]
    float* out_i = (float*)d_out + (size_t)NU * OD;  // [NI, OD]

    // --- degree counts (same edges both layers) ---
    launch_zero_i(cntB, NI);
    launch_zero_i(cntBB, NU);
    launch_zero_i(cntF, NU);
    launch_count(dst_buys, cntB, EB);
    launch_count(dst_bought, cntBB, EBB);
    launch_count(dst_follows, cntF, EF);

    // --- input projections ---
    launch_gemm(x_user, lin_u_W, nullptr, lin_u_b, nullptr,
                nullptr, nullptr, nullptr, nullptr, hu, NU, HD, FU, 1.f, 0);
    launch_gemm(x_item, lin_i_W, nullptr, lin_i_b, nullptr,
                nullptr, nullptr, nullptr, nullptr, hi, NI, HD, FI, 1.f, 0);

    // ================= layer 1 (H -> H) =================
    launch_zero_f(accI,  NI * HD);
    launch_zero_f(accU1, NU * HD);
    launch_zero_f(accU2, NU * HD);

    // buys: user -> item
    launch_gemm(hu, c1_buys_Wl, nullptr, nullptr, nullptr,
                nullptr, nullptr, nullptr, nullptr, y, NU, HD, HD, 1.f, 0);
    launch_scatter(y, src_buys, dst_buys, accI, EB, HD);
    // bought: item -> user
    launch_gemm(hi, c1_bought_Wl, nullptr, nullptr, nullptr,
                nullptr, nullptr, nullptr, nullptr, y, NI, HD, HD, 1.f, 0);
    launch_scatter(y, src_bought, dst_bought, accU1, EBB, HD);
    // follows: user -> user
    launch_gemm(hu, c1_follows_Wl, nullptr, nullptr, nullptr,
                nullptr, nullptr, nullptr, nullptr, y, NU, HD, HD, 1.f, 0);
    launch_scatter(y, src_follows, dst_follows, accU2, EF, HD);

    // item: relu(acc/deg + bl + hi@Wr)
    launch_gemm(hi, c1_buys_Wr, nullptr, c1_buys_bl, nullptr,
                accI, cntB, nullptr, nullptr, hi2, NI, HD, HD, 1.f, 1);
    // user: relu(0.5*(accU1/deg + bl_b + accU2/deg + bl_f + hu@(Wr_b+Wr_f)))
    launch_gemm(hu, c1_bought_Wr, c1_follows_Wr, c1_bought_bl, c1_follows_bl,
                accU1, cntBB, accU2, cntF, hu2, NU, HD, HD, 0.5f, 1);

    // ================= layer 2 (H -> O) =================
    launch_zero_f(accI,  NI * OD);
    launch_zero_f(accU1, NU * OD);
    launch_zero_f(accU2, NU * OD);

    launch_gemm(hu2, c2_buys_Wl, nullptr, nullptr, nullptr,
                nullptr, nullptr, nullptr, nullptr, y, NU, OD, HD, 1.f, 0);
    launch_scatter(y, src_buys, dst_buys, accI, EB, OD);
    launch_gemm(hi2, c2_bought_Wl, nullptr, nullptr, nullptr,
                nullptr, nullptr, nullptr, nullptr, y, NI, OD, HD, 1.f, 0);
    launch_scatter(y, src_bought, dst_bought, accU1, EBB, OD);
    launch_gemm(hu2, c2_follows_Wl, nullptr, nullptr, nullptr,
                nullptr, nullptr, nullptr, nullptr, y, NU, OD, HD, 1.f, 0);
    launch_scatter(y, src_follows, dst_follows, accU2, EF, OD);

    // outputs (no relu)
    launch_gemm(hi2, c2_buys_Wr, nullptr, c2_buys_bl, nullptr,
                accI, cntB, nullptr, nullptr, out_i, NI, OD, HD, 1.f, 0);
    launch_gemm(hu2, c2_bought_Wr, c2_follows_Wr, c2_bought_bl, c2_follows_bl,
                accU1, cntBB, accU2, cntF, out_u, NU, OD, HD, 0.5f, 0);

    (void)out_size;
}

// round 9
// speedup vs baseline: 1.2132x; 1.2132x over previous
#include <cuda_runtime.h>
#include <cuda_bf16.h>
#include <cstdint>

// Problem constants
#define NU 50000
#define NI 25000
#define FU 128
#define FI 64
#define HD 128
#define OD 64
#define EB  400000
#define EBB 400000
#define EF  200000

// ---------------- scratch (static device memory) ----------------------------
__device__ float g_hu  [NU * HD];
__device__ float g_hi  [NI * HD];
__device__ float g_hu2 [NU * HD];
__device__ float g_hi2 [NI * HD];
__device__ float g_y   [NU * HD];
__device__ float g_accU1[NU * HD];
__device__ float g_accU2[NU * HD];
__device__ float g_accI [NI * HD];
__device__ int   g_cntB [NI];
__device__ int   g_cntBB[NU];
__device__ int   g_cntF [NU];
// bf16 hi/lo transposed weights [N][K]
__device__ __nv_bfloat16 g_w_hi[147456];
__device__ __nv_bfloat16 g_w_lo[147456];

// weight offsets (elements)
#define W_LIN_U        0        // N=128,K=128
#define W_LIN_I        16384    // N=128,K=64
#define W_C1_BUYS_L    24576    // N=128,K=128
#define W_C1_BOUGHT_L  40960
#define W_C1_FOLLOWS_L 57344
#define W_C1_BUYS_R    73728
#define W_C1_USER_R    90112
#define W_C2_BUYS_L    106496   // N=64,K=128
#define W_C2_BOUGHT_L  114688
#define W_C2_FOLLOWS_L 122880
#define W_C2_BUYS_R    131072
#define W_C2_USER_R    139264

// ---------------- small utility kernels -------------------------------------
__global__ void zero_f_kernel(float* __restrict__ p, int n) {
    int t = blockIdx.x * blockDim.x + threadIdx.x;
    if (t < n) p[t] = 0.f;
}
__global__ void zero_i_kernel(int* __restrict__ p, int n) {
    int t = blockIdx.x * blockDim.x + threadIdx.x;
    if (t < n) p[t] = 0;
}
__global__ void count_deg_kernel(const int* __restrict__ dst, int* __restrict__ cnt, int E) {
    int t = blockIdx.x * blockDim.x + threadIdx.x;
    if (t < E) atomicAdd(&cnt[dst[t]], 1);
}
__device__ __forceinline__ uint16_t bfbits(__nv_bfloat16 h) {
    return *reinterpret_cast<uint16_t*>(&h);
}
// Wt[n*K+k] = hi/lo split of (W1[k*N+n] (+ W2[k*N+n]))
__global__ void prep_w_kernel(const float* __restrict__ W1, const float* __restrict__ W2,
                              __nv_bfloat16* __restrict__ hi, __nv_bfloat16* __restrict__ lo,
                              int K, int N) {
    int t = blockIdx.x * blockDim.x + threadIdx.x;
    if (t >= K * N) return;
    int n = t / K, k = t - n * K;
    float v = W1[k * N + n];
    if (W2) v += W2[k * N + n];
    __nv_bfloat16 h = __float2bfloat16_rn(v);
    hi[t] = h;
    lo[t] = __float2bfloat16_rn(v - __bfloat162float(h));
}
__global__ void scatter_add4_kernel(const float* __restrict__ y,
                                    const int* __restrict__ src,
                                    const int* __restrict__ dst,
                                    float* __restrict__ acc,
                                    int E, int N) {
    const int nq = N >> 2;
    const int total = E * nq;
    int t = blockIdx.x * blockDim.x + threadIdx.x;
    if (t >= total) return;
    int e = t / nq;
    int c = (t - e * nq) << 2;
    int s = src[e], d = dst[e];
    float4 v = *reinterpret_cast<const float4*>(&y[(size_t)s * N + c]);
    float* a = &acc[(size_t)d * N + c];
    atomicAdd(a + 0, v.x);
    atomicAdd(a + 1, v.y);
    atomicAdd(a + 2, v.z);
    atomicAdd(a + 3, v.w);
}

// ---------------- mma.sync helpers -------------------------------------------
__device__ __forceinline__ void ldsm_x4(uint32_t r[4], uint32_t saddr) {
    asm volatile("ldmatrix.sync.aligned.m8n8.x4.shared.b16 {%0,%1,%2,%3}, [%4];"
                 : "=r"(r[0]), "=r"(r[1]), "=r"(r[2]), "=r"(r[3]) : "r"(saddr));
}
__device__ __forceinline__ void mma_16816(float c[4], const uint32_t a[4],
                                          uint32_t b0, uint32_t b1) {
    asm volatile(
        "mma.sync.aligned.m16n8k16.row.col.f32.bf16.bf16.f32 "
        "{%0,%1,%2,%3}, {%4,%5,%6,%7}, {%8,%9}, {%0,%1,%2,%3};"
        : "+f"(c[0]), "+f"(c[1]), "+f"(c[2]), "+f"(c[3])
        : "r"(a[0]), "r"(a[1]), "r"(a[2]), "r"(a[3]), "r"(b0), "r"(b1));
}
__device__ __forceinline__ uint32_t smem_addr(const void* p) {
    return (uint32_t)__cvta_generic_to_shared(p);
}
__device__ __forceinline__ uint32_t pack_bf16(float x, float y) {
    __nv_bfloat16 hx = __float2bfloat16_rn(x);
    __nv_bfloat16 hy = __float2bfloat16_rn(y);
    return ((uint32_t)bfbits(hy) << 16) | bfbits(hx);
}

// ---------------- bf16x3 HMMA GEMM with fused SAGE epilogue -------------------
// C[m,n] = scale*( A@W + b1[n]+b2[n] + acc1[m,n]/max(cnt1,1) + acc2[m,n]/max(cnt2,1) )
// optional relu. W supplied transposed bf16 hi/lo [N][K]. BM=128, BN in {64,128}.
// K % 32 == 0.
template<int BN>
__global__ __launch_bounds__(256)
void mma_gemm_kernel(const float* __restrict__ A,
                     const __nv_bfloat16* __restrict__ Wh,
                     const __nv_bfloat16* __restrict__ Wl,
                     const float* __restrict__ b1, const float* __restrict__ b2,
                     const float* __restrict__ acc1, const int* __restrict__ cnt1,
                     const float* __restrict__ acc2, const int* __restrict__ cnt2,
                     float* __restrict__ C, int M, int K, float scale, int relu)
{
    constexpr int LDS = 40;              // padded row stride (bf16 elems) = 80B
    constexpr int NATOMS = BN / 16;      // n8 atoms per warp (warp N = BN/2)
    __shared__ __nv_bfloat16 Ah[128 * LDS];
    __shared__ __nv_bfloat16 Al[128 * LDS];
    __shared__ __nv_bfloat16 Bh[BN * LDS];
    __shared__ __nv_bfloat16 Bl[BN * LDS];

    const int tid  = threadIdx.x;
    const int wid  = tid >> 5;
    const int lane = tid & 31;
    const int bm   = blockIdx.x * 128;
    const int mbase = (wid & 3) * 32;        // warp M offset (2 m16 tiles)
    const int nbase = (wid >> 2) * (BN / 2); // warp N offset

    float acc[2][NATOMS][4];
    #pragma unroll
    for (int i = 0; i < 2; ++i)
        #pragma unroll
        for (int j = 0; j < NATOMS; ++j)
            #pragma unroll
            for (int q = 0; q < 4; ++q) acc[i][j][q] = 0.f;

    for (int k0 = 0; k0 < K; k0 += 32) {
        // ---- A tile: 128 x 32 fp32 -> bf16 hi/lo (split) ----
        #pragma unroll
        for (int it = 0; it < 4; ++it) {
            int idx = tid + it * 256;        // 0..1023 float4 slots
            int r = idx >> 3;
            int c4 = (idx & 7) << 2;
            int gm = bm + r;
            float4 v = make_float4(0.f, 0.f, 0.f, 0.f);
            if (gm < M)
                v = *reinterpret_cast<const float4*>(&A[(size_t)gm * K + k0 + c4]);
            float hx = __bfloat162float(__float2bfloat16_rn(v.x));
            float hy = __bfloat162float(__float2bfloat16_rn(v.y));
            float hz = __bfloat162float(__float2bfloat16_rn(v.z));
            float hw = __bfloat162float(__float2bfloat16_rn(v.w));
            uint2 hp, lp;
            hp.x = pack_bf16(v.x, v.y);
            hp.y = pack_bf16(v.z, v.w);
            lp.x = pack_bf16(v.x - hx, v.y - hy);
            lp.y = pack_bf16(v.z - hz, v.w - hw);
            *reinterpret_cast<uint2*>(&Ah[r * LDS + c4]) = hp;
            *reinterpret_cast<uint2*>(&Al[r * LDS + c4]) = lp;
        }
        // ---- B tile: BN x 32 bf16 hi/lo ----
        #pragma unroll
        for (int it = 0; it < BN / 32; ++it) {
            int idx = tid + it * 256;        // BN*8 slots of 4 bf16
            int n = idx >> 3;
            int c4 = (idx & 7) << 2;
            uint2 hv = *reinterpret_cast<const uint2*>(Wh + (size_t)n * K + k0 + c4);
            uint2 lv = *reinterpret_cast<const uint2*>(Wl + (size_t)n * K + k0 + c4);
            *reinterpret_cast<uint2*>(&Bh[n * LDS + c4]) = hv;
            *reinterpret_cast<uint2*>(&Bl[n * LDS + c4]) = lv;
        }
        __syncthreads();

        #pragma unroll
        for (int kk = 0; kk < 32; kk += 16) {
            // A fragments: rows mbase + i*16 + (lane%16), col kk + 8*(lane/16)
            uint32_t ah[2][4], al[2][4];
            const int ar = lane & 15;
            const int ac = kk + ((lane >> 4) << 3);
            #pragma unroll
            for (int i = 0; i < 2; ++i) {
                ldsm_x4(ah[i], smem_addr(&Ah[(mbase + i * 16 + ar) * LDS + ac]));
                ldsm_x4(al[i], smem_addr(&Al[(mbase + i * 16 + ar) * LDS + ac]));
            }
            // B fragments: rows n + (lane&7) + 8*(lane>>4), col kk + 8*((lane>>3)&1)
            const int br = (lane & 7) + ((lane >> 4) << 3);
            const int bc = kk + (((lane >> 3) & 1) << 3);
            #pragma unroll
            for (int j2 = 0; j2 < NATOMS / 2; ++j2) {
                uint32_t bh[4], bl[4];
                int n0 = nbase + j2 * 16;
                ldsm_x4(bh, smem_addr(&Bh[(n0 + br) * LDS + bc]));
                ldsm_x4(bl, smem_addr(&Bl[(n0 + br) * LDS + bc]));
                #pragma unroll
                for (int i = 0; i < 2; ++i) {
                    mma_16816(acc[i][2 * j2],     ah[i], bh[0], bh[1]);
                    mma_16816(acc[i][2 * j2 + 1], ah[i], bh[2], bh[3]);
                    mma_16816(acc[i][2 * j2],     ah[i], bl[0], bl[1]);
                    mma_16816(acc[i][2 * j2 + 1], ah[i], bl[2], bl[3]);
                    mma_16816(acc[i][2 * j2],     al[i], bh[0], bh[1]);
                    mma_16816(acc[i][2 * j2 + 1], al[i], bh[2], bh[3]);
                }
            }
        }
        __syncthreads();
    }

    // ---- epilogue ----
    const int qr = lane >> 2;          // row within m16 half
    const int qc = (lane & 3) << 1;    // col pair within n8
    #pragma unroll
    for (int i = 0; i < 2; ++i) {
        #pragma unroll
        for (int h = 0; h < 2; ++h) {
            int m = bm + mbase + i * 16 + qr + 8 * h;
            if (m >= M) continue;
            float inv1 = 0.f, inv2 = 0.f;
            if (cnt1) { int c = cnt1[m]; inv1 = 1.f / (float)(c > 0 ? c : 1); }
            if (cnt2) { int c = cnt2[m]; inv2 = 1.f / (float)(c > 0 ? c : 1); }
            #pragma unroll
            for (int j = 0; j < NATOMS; ++j) {
                int n = nbase + j * 8 + qc;
                float v0 = acc[i][j][2 * h + 0];
                float v1 = acc[i][j][2 * h + 1];
                if (b1) { v0 += b1[n]; v1 += b1[n + 1]; }
                if (b2) { v0 += b2[n]; v1 += b2[n + 1]; }
                if (acc1) {
                    float2 a = *reinterpret_cast<const float2*>(&acc1[(size_t)m * BN + n]);
                    v0 += a.x * inv1; v1 += a.y * inv1;
                }
                if (acc2) {
                    float2 a = *reinterpret_cast<const float2*>(&acc2[(size_t)m * BN + n]);
                    v0 += a.x * inv2; v1 += a.y * inv2;
                }
                v0 *= scale; v1 *= scale;
                if (relu) { v0 = fmaxf(v0, 0.f); v1 = fmaxf(v1, 0.f); }
                float2 o; o.x = v0; o.y = v1;
                *reinterpret_cast<float2*>(&C[(size_t)m * BN + n]) = o;
            }
        }
    }
}

// ---------------- host side --------------------------------------------------
static inline void launch_zero_f(float* p, int n) {
    zero_f_kernel<<<(n + 255) / 256, 256>>>(p, n);
}
static inline void launch_zero_i(int* p, int n) {
    zero_i_kernel<<<(n + 255) / 256, 256>>>(p, n);
}
static inline void launch_count(const int* dst, int* cnt, int E) {
    count_deg_kernel<<<(E + 255) / 256, 256>>>(dst, cnt, E);
}
static inline void launch_scatter(const float* y, const int* src, const int* dst,
                                  float* acc, int E, int N) {
    int total = E * (N >> 2);
    scatter_add4_kernel<<<(total + 255) / 256, 256>>>(y, src, dst, acc, E, N);
}
static inline void launch_prep(const float* W1, const float* W2,
                               __nv_bfloat16* hi, __nv_bfloat16* lo, int K, int N) {
    int n = K * N;
    prep_w_kernel<<<(n + 255) / 256, 256>>>(W1, W2, hi, lo, K, N);
}
template<int BN>
static inline void launch_mma(const float* A, const __nv_bfloat16* Wh, const __nv_bfloat16* Wl,
                              const float* b1, const float* b2,
                              const float* acc1, const int* cnt1,
                              const float* acc2, const int* cnt2,
                              float* C, int M, int K, float scale, int relu) {
    mma_gemm_kernel<BN><<<(M + 127) / 128, 256>>>(
        A, Wh, Wl, b1, b2, acc1, cnt1, acc2, cnt2, C, M, K, scale, relu);
}

extern "C" void kernel_launch(void* const* d_in, const int* in_sizes, int n_in,
                              void* d_out, int out_size) {
    (void)in_sizes; (void)n_in; (void)out_size;
    const float* x_user      = (const float*)d_in[0];
    const float* x_item      = (const float*)d_in[1];
    const int*   src_buys    = (const int*)d_in[2];
    const int*   dst_buys    = (const int*)d_in[3];
    const int*   src_bought  = (const int*)d_in[4];
    const int*   dst_bought  = (const int*)d_in[5];
    const int*   src_follows = (const int*)d_in[6];
    const int*   dst_follows = (const int*)d_in[7];
    const float* lin_u_W = (const float*)d_in[8];
    const float* lin_u_b = (const float*)d_in[9];
    const float* lin_i_W = (const float*)d_in[10];
    const float* lin_i_b = (const float*)d_in[11];
    const float* c1_buys_Wl    = (const float*)d_in[12];
    const float* c1_buys_bl    = (const float*)d_in[13];
    const float* c1_buys_Wr    = (const float*)d_in[14];
    const float* c1_bought_Wl  = (const float*)d_in[15];
    const float* c1_bought_bl  = (const float*)d_in[16];
    const float* c1_bought_Wr  = (const float*)d_in[17];
    const float* c1_follows_Wl = (const float*)d_in[18];
    const float* c1_follows_bl = (const float*)d_in[19];
    const float* c1_follows_Wr = (const float*)d_in[20];
    const float* c2_buys_Wl    = (const float*)d_in[21];
    const float* c2_buys_bl    = (const float*)d_in[22];
    const float* c2_buys_Wr    = (const float*)d_in[23];
    const float* c2_bought_Wl  = (const float*)d_in[24];
    const float* c2_bought_bl  = (const float*)d_in[25];
    const float* c2_bought_Wr  = (const float*)d_in[26];
    const float* c2_follows_Wl = (const float*)d_in[27];
    const float* c2_follows_bl = (const float*)d_in[28];
    const float* c2_follows_Wr = (const float*)d_in[29];

    void *p;
    float *hu, *hi, *hu2, *hi2, *y, *accU1, *accU2, *accI;
    int *cntB, *cntBB, *cntF;
    __nv_bfloat16 *wh, *wl;
    cudaGetSymbolAddress(&p, g_hu);    hu    = (float*)p;
    cudaGetSymbolAddress(&p, g_hi);    hi    = (float*)p;
    cudaGetSymbolAddress(&p, g_hu2);   hu2   = (float*)p;
    cudaGetSymbolAddress(&p, g_hi2);   hi2   = (float*)p;
    cudaGetSymbolAddress(&p, g_y);     y     = (float*)p;
    cudaGetSymbolAddress(&p, g_accU1); accU1 = (float*)p;
    cudaGetSymbolAddress(&p, g_accU2); accU2 = (float*)p;
    cudaGetSymbolAddress(&p, g_accI);  accI  = (float*)p;
    cudaGetSymbolAddress(&p, g_cntB);  cntB  = (int*)p;
    cudaGetSymbolAddress(&p, g_cntBB); cntBB = (int*)p;
    cudaGetSymbolAddress(&p, g_cntF);  cntF  = (int*)p;
    cudaGetSymbolAddress(&p, g_w_hi);  wh    = (__nv_bfloat16*)p;
    cudaGetSymbolAddress(&p, g_w_lo);  wl    = (__nv_bfloat16*)p;

    float* out_u = (float*)d_out;
    float* out_i = (float*)d_out + (size_t)NU * OD;

    // --- degrees ---
    launch_zero_i(cntB, NI);
    launch_zero_i(cntBB, NU);
    launch_zero_i(cntF, NU);
    launch_count(dst_buys, cntB, EB);
    launch_count(dst_bought, cntBB, EBB);
    launch_count(dst_follows, cntF, EF);

    // --- weight prep (transposed bf16 hi/lo) ---
    launch_prep(lin_u_W, nullptr,      wh + W_LIN_U,       wl + W_LIN_U,       FU, HD);
    launch_prep(lin_i_W, nullptr,      wh + W_LIN_I,       wl + W_LIN_I,       FI, HD);
    launch_prep(c1_buys_Wl, nullptr,   wh + W_C1_BUYS_L,   wl + W_C1_BUYS_L,   HD, HD);
    launch_prep(c1_bought_Wl, nullptr, wh + W_C1_BOUGHT_L, wl + W_C1_BOUGHT_L, HD, HD);
    launch_prep(c1_follows_Wl, nullptr,wh + W_C1_FOLLOWS_L,wl + W_C1_FOLLOWS_L,HD, HD);
    launch_prep(c1_buys_Wr, nullptr,   wh + W_C1_BUYS_R,   wl + W_C1_BUYS_R,   HD, HD);
    launch_prep(c1_bought_Wr, c1_follows_Wr, wh + W_C1_USER_R, wl + W_C1_USER_R, HD, HD);
    launch_prep(c2_buys_Wl, nullptr,   wh + W_C2_BUYS_L,   wl + W_C2_BUYS_L,   HD, OD);
    launch_prep(c2_bought_Wl, nullptr, wh + W_C2_BOUGHT_L, wl + W_C2_BOUGHT_L, HD, OD);
    launch_prep(c2_follows_Wl, nullptr,wh + W_C2_FOLLOWS_L,wl + W_C2_FOLLOWS_L,HD, OD);
    launch_prep(c2_buys_Wr, nullptr,   wh + W_C2_BUYS_R,   wl + W_C2_BUYS_R,   HD, OD);
    launch_prep(c2_bought_Wr, c2_follows_Wr, wh + W_C2_USER_R, wl + W_C2_USER_R, HD, OD);

    // --- input projections ---
    launch_mma<128>(x_user, wh + W_LIN_U, wl + W_LIN_U, lin_u_b, nullptr,
                    nullptr, nullptr, nullptr, nullptr, hu, NU, FU, 1.f, 0);
    launch_mma<128>(x_item, wh + W_LIN_I, wl + W_LIN_I, lin_i_b, nullptr,
                    nullptr, nullptr, nullptr, nullptr, hi, NI, FI, 1.f, 0);

    // ================= layer 1 (H -> H) =================
    launch_zero_f(accI,  NI * HD);
    launch_zero_f(accU1, NU * HD);
    launch_zero_f(accU2, NU * HD);

    launch_mma<128>(hu, wh + W_C1_BUYS_L, wl + W_C1_BUYS_L, nullptr, nullptr,
                    nullptr, nullptr, nullptr, nullptr, y, NU, HD, 1.f, 0);
    launch_scatter(y, src_buys, dst_buys, accI, EB, HD);
    launch_mma<128>(hi, wh + W_C1_BOUGHT_L, wl + W_C1_BOUGHT_L, nullptr, nullptr,
                    nullptr, nullptr, nullptr, nullptr, y, NI, HD, 1.f, 0);
    launch_scatter(y, src_bought, dst_bought, accU1, EBB, HD);
    launch_mma<128>(hu, wh + W_C1_FOLLOWS_L, wl + W_C1_FOLLOWS_L, nullptr, nullptr,
                    nullptr, nullptr, nullptr, nullptr, y, NU, HD, 1.f, 0);
    launch_scatter(y, src_follows, dst_follows, accU2, EF, HD);

    launch_mma<128>(hi, wh + W_C1_BUYS_R, wl + W_C1_BUYS_R, c1_buys_bl, nullptr,
                    accI, cntB, nullptr, nullptr, hi2, NI, HD, 1.f, 1);
    launch_mma<128>(hu, wh + W_C1_USER_R, wl + W_C1_USER_R, c1_bought_bl, c1_follows_bl,
                    accU1, cntBB, accU2, cntF, hu2, NU, HD, 0.5f, 1);

    // ================= layer 2 (H -> O) =================
    launch_zero_f(accI,  NI * OD);
    launch_zero_f(accU1, NU * OD);
    launch_zero_f(accU2, NU * OD);

    launch_mma<64>(hu2, wh + W_C2_BUYS_L, wl + W_C2_BUYS_L, nullptr, nullptr,
                   nullptr, nullptr, nullptr, nullptr, y, NU, HD, 1.f, 0);
    launch_scatter(y, src_buys, dst_buys, accI, EB, OD);
    launch_mma<64>(hi2, wh + W_C2_BOUGHT_L, wl + W_C2_BOUGHT_L, nullptr, nullptr,
                   nullptr, nullptr, nullptr, nullptr, y, NI, HD, 1.f, 0);
    launch_scatter(y, src_bought, dst_bought, accU1, EBB, OD);
    launch_mma<64>(hu2, wh + W_C2_FOLLOWS_L, wl + W_C2_FOLLOWS_L, nullptr, nullptr,
                   nullptr, nullptr, nullptr, nullptr, y, NU, HD, 1.f, 0);
    launch_scatter(y, src_follows, dst_follows, accU2, EF, OD);

    launch_mma<64>(hi2, wh + W_C2_BUYS_R, wl + W_C2_BUYS_R, c2_buys_bl, nullptr,
                   accI, cntB, nullptr, nullptr, out_i, NI, HD, 1.f, 0);
    launch_mma<64>(hu2, wh + W_C2_USER_R, wl + W_C2_USER_R, c2_bought_bl, c2_follows_bl,
                   accU1, cntBB, accU2, cntF, out_u, NU, HD, 0.5f, 0);
}

// round 12
// speedup vs baseline: 1.5559x; 1.2825x over previous
#include <cuda_runtime.h>
#include <cuda_bf16.h>
#include <cstdint>

// Problem constants
#define NU 50000
#define NI 25000
#define FU 128
#define FI 64
#define HD 128
#define OD 64
#define EB  400000
#define EBB 400000
#define EF  200000

// ---------------- scratch (static device memory) ----------------------------
__device__ float g_hu  [NU * HD];
__device__ float g_hi  [NI * HD];
__device__ float g_hu2 [NU * HD];
__device__ float g_hi2 [NI * HD];
__device__ float g_y   [NU * HD];
__device__ float g_accU1[NU * HD];
__device__ float g_accU2[NU * HD];
__device__ float g_accI [NI * HD];
__device__ int   g_cntB [NI];
__device__ int   g_cntBB[NU];
__device__ int   g_cntF [NU];
// CSR edge lists (src sorted by dst) + offsets/cursors
__device__ int   g_srtB [EB];
__device__ int   g_srtBB[EBB];
__device__ int   g_srtF [EF];
__device__ int   g_offB [NI];
__device__ int   g_curB [NI];
__device__ int   g_offBB[NU];
__device__ int   g_curBB[NU];
__device__ int   g_offF [NU];
__device__ int   g_curF [NU];
// bf16 hi/lo transposed weights [N][K]
__device__ __nv_bfloat16 g_w_hi[147456];
__device__ __nv_bfloat16 g_w_lo[147456];

// weight offsets (elements)
#define W_LIN_U        0        // N=128,K=128
#define W_LIN_I        16384    // N=128,K=64
#define W_C1_BUYS_L    24576    // N=128,K=128
#define W_C1_BOUGHT_L  40960
#define W_C1_FOLLOWS_L 57344
#define W_C1_BUYS_R    73728
#define W_C1_USER_R    90112
#define W_C2_BUYS_L    106496   // N=64,K=128
#define W_C2_BOUGHT_L  114688
#define W_C2_FOLLOWS_L 122880
#define W_C2_BUYS_R    131072
#define W_C2_USER_R    139264

// ---------------- small utility kernels -------------------------------------
__global__ void zero_i_kernel(int* __restrict__ p, int n) {
    int t = blockIdx.x * blockDim.x + threadIdx.x;
    if (t < n) p[t] = 0;
}
__global__ void count_deg_kernel(const int* __restrict__ dst, int* __restrict__ cnt, int E) {
    int t = blockIdx.x * blockDim.x + threadIdx.x;
    if (t < E) atomicAdd(&cnt[dst[t]], 1);
}
// single-block exclusive scan: off[i] = cur[i] = sum(cnt[0..i-1])
__global__ void scan_kernel(const int* __restrict__ cnt, int* __restrict__ off,
                            int* __restrict__ cur, int n) {
    __shared__ int buf[1024];
    __shared__ int carry_s;
    const int tid = threadIdx.x;
    if (tid == 0) carry_s = 0;
    __syncthreads();
    for (int base = 0; base < n; base += 1024) {
        int i = base + tid;
        int v = (i < n) ? cnt[i] : 0;
        buf[tid] = v;
        __syncthreads();
        #pragma unroll
        for (int d = 1; d < 1024; d <<= 1) {
            int t = (tid >= d) ? buf[tid - d] : 0;
            __syncthreads();
            buf[tid] += t;
            __syncthreads();
        }
        int excl = buf[tid] - v;
        if (i < n) { int o = carry_s + excl; off[i] = o; cur[i] = o; }
        __syncthreads();
        if (tid == 1023) carry_s += buf[1023];
        __syncthreads();
    }
}
// place src of each edge into dst-sorted array
__global__ void fill_csr_kernel(const int* __restrict__ src, const int* __restrict__ dst,
                                int* __restrict__ cur, int* __restrict__ srt, int E) {
    int t = blockIdx.x * blockDim.x + threadIdx.x;
    if (t >= E) return;
    int d = dst[t];
    int pos = atomicAdd(&cur[d], 1);
    srt[pos] = src[t];
}
// gather: acc[node,:] = sum over CSR edges of y[src,:]   (one warp per node)
template<int N>
__global__ void gather_kernel(const float* __restrict__ y,
                              const int* __restrict__ off, const int* __restrict__ cnt,
                              const int* __restrict__ srt,
                              float* __restrict__ acc, int nodes) {
    int node = (blockIdx.x * blockDim.x + threadIdx.x) >> 5;
    if (node >= nodes) return;
    const int lane = threadIdx.x & 31;
    const int s = off[node];
    const int e = s + cnt[node];
    if (N == 128) {
        const int col = lane << 2;
        float4 v0 = make_float4(0.f, 0.f, 0.f, 0.f);
        float4 v1 = make_float4(0.f, 0.f, 0.f, 0.f);
        int i = s;
        for (; i + 1 < e; i += 2) {
            int s0 = srt[i], s1 = srt[i + 1];
            float4 u0 = *reinterpret_cast<const float4*>(&y[(size_t)s0 * 128 + col]);
            float4 u1 = *reinterpret_cast<const float4*>(&y[(size_t)s1 * 128 + col]);
            v0.x += u0.x; v0.y += u0.y; v0.z += u0.z; v0.w += u0.w;
            v1.x += u1.x; v1.y += u1.y; v1.z += u1.z; v1.w += u1.w;
        }
        if (i < e) {
            float4 u = *reinterpret_cast<const float4*>(&y[(size_t)srt[i] * 128 + col]);
            v0.x += u.x; v0.y += u.y; v0.z += u.z; v0.w += u.w;
        }
        v0.x += v1.x; v0.y += v1.y; v0.z += v1.z; v0.w += v1.w;
        *reinterpret_cast<float4*>(&acc[(size_t)node * 128 + col]) = v0;
    } else {
        const int col = lane << 1;
        float2 v0 = make_float2(0.f, 0.f);
        float2 v1 = make_float2(0.f, 0.f);
        int i = s;
        for (; i + 1 < e; i += 2) {
            int s0 = srt[i], s1 = srt[i + 1];
            float2 u0 = *reinterpret_cast<const float2*>(&y[(size_t)s0 * 64 + col]);
            float2 u1 = *reinterpret_cast<const float2*>(&y[(size_t)s1 * 64 + col]);
            v0.x += u0.x; v0.y += u0.y;
            v1.x += u1.x; v1.y += u1.y;
        }
        if (i < e) {
            float2 u = *reinterpret_cast<const float2*>(&y[(size_t)srt[i] * 64 + col]);
            v0.x += u.x; v0.y += u.y;
        }
        v0.x += v1.x; v0.y += v1.y;
        *reinterpret_cast<float2*>(&acc[(size_t)node * 64 + col]) = v0;
    }
}

__device__ __forceinline__ uint16_t bfbits(__nv_bfloat16 h) {
    return *reinterpret_cast<uint16_t*>(&h);
}
// Wt[n*K+k] = hi/lo split of (W1[k*N+n] (+ W2[k*N+n]))
__global__ void prep_w_kernel(const float* __restrict__ W1, const float* __restrict__ W2,
                              __nv_bfloat16* __restrict__ hi, __nv_bfloat16* __restrict__ lo,
                              int K, int N) {
    int t = blockIdx.x * blockDim.x + threadIdx.x;
    if (t >= K * N) return;
    int n = t / K, k = t - n * K;
    float v = W1[k * N + n];
    if (W2) v += W2[k * N + n];
    __nv_bfloat16 h = __float2bfloat16_rn(v);
    hi[t] = h;
    lo[t] = __float2bfloat16_rn(v - __bfloat162float(h));
}

// ---------------- mma.sync helpers -------------------------------------------
__device__ __forceinline__ void ldsm_x4(uint32_t r[4], uint32_t saddr) {
    asm volatile("ldmatrix.sync.aligned.m8n8.x4.shared.b16 {%0,%1,%2,%3}, [%4];"
                 : "=r"(r[0]), "=r"(r[1]), "=r"(r[2]), "=r"(r[3]) : "r"(saddr));
}
__device__ __forceinline__ void mma_16816(float c[4], const uint32_t a[4],
                                          uint32_t b0, uint32_t b1) {
    asm volatile(
        "mma.sync.aligned.m16n8k16.row.col.f32.bf16.bf16.f32 "
        "{%0,%1,%2,%3}, {%4,%5,%6,%7}, {%8,%9}, {%0,%1,%2,%3};"
        : "+f"(c[0]), "+f"(c[1]), "+f"(c[2]), "+f"(c[3])
        : "r"(a[0]), "r"(a[1]), "r"(a[2]), "r"(a[3]), "r"(b0), "r"(b1));
}
__device__ __forceinline__ uint32_t smem_addr(const void* p) {
    return (uint32_t)__cvta_generic_to_shared(p);
}
__device__ __forceinline__ uint32_t pack_bf16(float x, float y) {
    __nv_bfloat16 hx = __float2bfloat16_rn(x);
    __nv_bfloat16 hy = __float2bfloat16_rn(y);
    return ((uint32_t)bfbits(hy) << 16) | bfbits(hx);
}

// ---------------- bf16x3 HMMA GEMM with fused SAGE epilogue -------------------
// C[m,n] = scale*( A@W + b1[n]+b2[n] + acc1[m,n]/max(cnt1,1) + acc2[m,n]/max(cnt2,1) )
// optional relu. W supplied transposed bf16 hi/lo [N][K]. BM=128, BN in {64,128}.
// K % 32 == 0.
template<int BN>
__global__ __launch_bounds__(256)
void mma_gemm_kernel(const float* __restrict__ A,
                     const __nv_bfloat16* __restrict__ Wh,
                     const __nv_bfloat16* __restrict__ Wl,
                     const float* __restrict__ b1, const float* __restrict__ b2,
                     const float* __restrict__ acc1, const int* __restrict__ cnt1,
                     const float* __restrict__ acc2, const int* __restrict__ cnt2,
                     float* __restrict__ C, int M, int K, float scale, int relu)
{
    constexpr int LDS = 40;              // padded row stride (bf16 elems) = 80B
    constexpr int NATOMS = BN / 16;      // n8 atoms per warp (warp N = BN/2)
    __shared__ __nv_bfloat16 Ah[128 * LDS];
    __shared__ __nv_bfloat16 Al[128 * LDS];
    __shared__ __nv_bfloat16 Bh[BN * LDS];
    __shared__ __nv_bfloat16 Bl[BN * LDS];

    const int tid  = threadIdx.x;
    const int wid  = tid >> 5;
    const int lane = tid & 31;
    const int bm   = blockIdx.x * 128;
    const int mbase = (wid & 3) * 32;        // warp M offset (2 m16 tiles)
    const int nbase = (wid >> 2) * (BN / 2); // warp N offset

    float acc[2][NATOMS][4];
    #pragma unroll
    for (int i = 0; i < 2; ++i)
        #pragma unroll
        for (int j = 0; j < NATOMS; ++j)
            #pragma unroll
            for (int q = 0; q < 4; ++q) acc[i][j][q] = 0.f;

    for (int k0 = 0; k0 < K; k0 += 32) {
        // ---- A tile: 128 x 32 fp32 -> bf16 hi/lo (split) ----
        #pragma unroll
        for (int it = 0; it < 4; ++it) {
            int idx = tid + it * 256;        // 0..1023 float4 slots
            int r = idx >> 3;
            int c4 = (idx & 7) << 2;
            int gm = bm + r;
            float4 v = make_float4(0.f, 0.f, 0.f, 0.f);
            if (gm < M)
                v = *reinterpret_cast<const float4*>(&A[(size_t)gm * K + k0 + c4]);
            float hx = __bfloat162float(__float2bfloat16_rn(v.x));
            float hy = __bfloat162float(__float2bfloat16_rn(v.y));
            float hz = __bfloat162float(__float2bfloat16_rn(v.z));
            float hw = __bfloat162float(__float2bfloat16_rn(v.w));
            uint2 hp, lp;
            hp.x = pack_bf16(v.x, v.y);
            hp.y = pack_bf16(v.z, v.w);
            lp.x = pack_bf16(v.x - hx, v.y - hy);
            lp.y = pack_bf16(v.z - hz, v.w - hw);
            *reinterpret_cast<uint2*>(&Ah[r * LDS + c4]) = hp;
            *reinterpret_cast<uint2*>(&Al[r * LDS + c4]) = lp;
        }
        // ---- B tile: BN x 32 bf16 hi/lo ----
        #pragma unroll
        for (int it = 0; it < BN / 32; ++it) {
            int idx = tid + it * 256;        // BN*8 slots of 4 bf16
            int n = idx >> 3;
            int c4 = (idx & 7) << 2;
            uint2 hv = *reinterpret_cast<const uint2*>(Wh + (size_t)n * K + k0 + c4);
            uint2 lv = *reinterpret_cast<const uint2*>(Wl + (size_t)n * K + k0 + c4);
            *reinterpret_cast<uint2*>(&Bh[n * LDS + c4]) = hv;
            *reinterpret_cast<uint2*>(&Bl[n * LDS + c4]) = lv;
        }
        __syncthreads();

        #pragma unroll
        for (int kk = 0; kk < 32; kk += 16) {
            // A fragments: rows mbase + i*16 + (lane%16), col kk + 8*(lane/16)
            uint32_t ah[2][4], al[2][4];
            const int ar = lane & 15;
            const int ac = kk + ((lane >> 4) << 3);
            #pragma unroll
            for (int i = 0; i < 2; ++i) {
                ldsm_x4(ah[i], smem_addr(&Ah[(mbase + i * 16 + ar) * LDS + ac]));
                ldsm_x4(al[i], smem_addr(&Al[(mbase + i * 16 + ar) * LDS + ac]));
            }
            // B fragments: rows n + (lane&7) + 8*(lane>>4), col kk + 8*((lane>>3)&1)
            const int br = (lane & 7) + ((lane >> 4) << 3);
            const int bc = kk + (((lane >> 3) & 1) << 3);
            #pragma unroll
            for (int j2 = 0; j2 < NATOMS / 2; ++j2) {
                uint32_t bh[4], bl[4];
                int n0 = nbase + j2 * 16;
                ldsm_x4(bh, smem_addr(&Bh[(n0 + br) * LDS + bc]));
                ldsm_x4(bl, smem_addr(&Bl[(n0 + br) * LDS + bc]));
                #pragma unroll
                for (int i = 0; i < 2; ++i) {
                    mma_16816(acc[i][2 * j2],     ah[i], bh[0], bh[1]);
                    mma_16816(acc[i][2 * j2 + 1], ah[i], bh[2], bh[3]);
                    mma_16816(acc[i][2 * j2],     ah[i], bl[0], bl[1]);
                    mma_16816(acc[i][2 * j2 + 1], ah[i], bl[2], bl[3]);
                    mma_16816(acc[i][2 * j2],     al[i], bh[0], bh[1]);
                    mma_16816(acc[i][2 * j2 + 1], al[i], bh[2], bh[3]);
                }
            }
        }
        __syncthreads();
    }

    // ---- epilogue ----
    const int qr = lane >> 2;          // row within m16 half
    const int qc = (lane & 3) << 1;    // col pair within n8
    #pragma unroll
    for (int i = 0; i < 2; ++i) {
        #pragma unroll
        for (int h = 0; h < 2; ++h) {
            int m = bm + mbase + i * 16 + qr + 8 * h;
            if (m >= M) continue;
            float inv1 = 0.f, inv2 = 0.f;
            if (cnt1) { int c = cnt1[m]; inv1 = 1.f / (float)(c > 0 ? c : 1); }
            if (cnt2) { int c = cnt2[m]; inv2 = 1.f / (float)(c > 0 ? c : 1); }
            #pragma unroll
            for (int j = 0; j < NATOMS; ++j) {
                int n = nbase + j * 8 + qc;
                float v0 = acc[i][j][2 * h + 0];
                float v1 = acc[i][j][2 * h + 1];
                if (b1) { v0 += b1[n]; v1 += b1[n + 1]; }
                if (b2) { v0 += b2[n]; v1 += b2[n + 1]; }
                if (acc1) {
                    float2 a = *reinterpret_cast<const float2*>(&acc1[(size_t)m * BN + n]);
                    v0 += a.x * inv1; v1 += a.y * inv1;
                }
                if (acc2) {
                    float2 a = *reinterpret_cast<const float2*>(&acc2[(size_t)m * BN + n]);
                    v0 += a.x * inv2; v1 += a.y * inv2;
                }
                v0 *= scale; v1 *= scale;
                if (relu) { v0 = fmaxf(v0, 0.f); v1 = fmaxf(v1, 0.f); }
                float2 o; o.x = v0; o.y = v1;
                *reinterpret_cast<float2*>(&C[(size_t)m * BN + n]) = o;
            }
        }
    }
}

// ---------------- host side --------------------------------------------------
static inline void launch_zero_i(int* p, int n) {
    zero_i_kernel<<<(n + 255) / 256, 256>>>(p, n);
}
static inline void launch_count(const int* dst, int* cnt, int E) {
    count_deg_kernel<<<(E + 255) / 256, 256>>>(dst, cnt, E);
}
static inline void launch_scan(const int* cnt, int* off, int* cur, int n) {
    scan_kernel<<<1, 1024>>>(cnt, off, cur, n);
}
static inline void launch_fill(const int* src, const int* dst, int* cur, int* srt, int E) {
    fill_csr_kernel<<<(E + 255) / 256, 256>>>(src, dst, cur, srt, E);
}
template<int N>
static inline void launch_gather(const float* y, const int* off, const int* cnt,
                                 const int* srt, float* acc, int nodes) {
    int threads = nodes * 32;
    gather_kernel<N><<<(threads + 255) / 256, 256>>>(y, off, cnt, srt, acc, nodes);
}
static inline void launch_prep(const float* W1, const float* W2,
                               __nv_bfloat16* hi, __nv_bfloat16* lo, int K, int N) {
    int n = K * N;
    prep_w_kernel<<<(n + 255) / 256, 256>>>(W1, W2, hi, lo, K, N);
}
template<int BN>
static inline void launch_mma(const float* A, const __nv_bfloat16* Wh, const __nv_bfloat16* Wl,
                              const float* b1, const float* b2,
                              const float* acc1, const int* cnt1,
                              const float* acc2, const int* cnt2,
                              float* C, int M, int K, float scale, int relu) {
    mma_gemm_kernel<BN><<<(M + 127) / 128, 256>>>(
        A, Wh, Wl, b1, b2, acc1, cnt1, acc2, cnt2, C, M, K, scale, relu);
}

extern "C" void kernel_launch(void* const* d_in, const int* in_sizes, int n_in,
                              void* d_out, int out_size) {
    (void)in_sizes; (void)n_in; (void)out_size;
    const float* x_user      = (const float*)d_in[0];
    const float* x_item      = (const float*)d_in[1];
    const int*   src_buys    = (const int*)d_in[2];
    const int*   dst_buys    = (const int*)d_in[3];
    const int*   src_bought  = (const int*)d_in[4];
    const int*   dst_bought  = (const int*)d_in[5];
    const int*   src_follows = (const int*)d_in[6];
    const int*   dst_follows = (const int*)d_in[7];
    const float* lin_u_W = (const float*)d_in[8];
    const float* lin_u_b = (const float*)d_in[9];
    const float* lin_i_W = (const float*)d_in[10];
    const float* lin_i_b = (const float*)d_in[11];
    const float* c1_buys_Wl    = (const float*)d_in[12];
    const float* c1_buys_bl    = (const float*)d_in[13];
    const float* c1_buys_Wr    = (const float*)d_in[14];
    const float* c1_bought_Wl  = (const float*)d_in[15];
    const float* c1_bought_bl  = (const float*)d_in[16];
    const float* c1_bought_Wr  = (const float*)d_in[17];
    const float* c1_follows_Wl = (const float*)d_in[18];
    const float* c1_follows_bl = (const float*)d_in[19];
    const float* c1_follows_Wr = (const float*)d_in[20];
    const float* c2_buys_Wl    = (const float*)d_in[21];
    const float* c2_buys_bl    = (const float*)d_in[22];
    const float* c2_buys_Wr    = (const float*)d_in[23];
    const float* c2_bought_Wl  = (const float*)d_in[24];
    const float* c2_bought_bl  = (const float*)d_in[25];
    const float* c2_bought_Wr  = (const float*)d_in[26];
    const float* c2_follows_Wl = (const float*)d_in[27];
    const float* c2_follows_bl = (const float*)d_in[28];
    const float* c2_follows_Wr = (const float*)d_in[29];

    void *p;
    float *hu, *hi, *hu2, *hi2, *y, *accU1, *accU2, *accI;
    int *cntB, *cntBB, *cntF;
    int *srtB, *srtBB, *srtF, *offB, *curB, *offBB, *curBB, *offF, *curF;
    __nv_bfloat16 *wh, *wl;
    cudaGetSymbolAddress(&p, g_hu);    hu    = (float*)p;
    cudaGetSymbolAddress(&p, g_hi);    hi    = (float*)p;
    cudaGetSymbolAddress(&p, g_hu2);   hu2   = (float*)p;
    cudaGetSymbolAddress(&p, g_hi2);   hi2   = (float*)p;
    cudaGetSymbolAddress(&p, g_y);     y     = (float*)p;
    cudaGetSymbolAddress(&p, g_accU1); accU1 = (float*)p;
    cudaGetSymbolAddress(&p, g_accU2); accU2 = (float*)p;
    cudaGetSymbolAddress(&p, g_accI);  accI  = (float*)p;
    cudaGetSymbolAddress(&p, g_cntB);  cntB  = (int*)p;
    cudaGetSymbolAddress(&p, g_cntBB); cntBB = (int*)p;
    cudaGetSymbolAddress(&p, g_cntF);  cntF  = (int*)p;
    cudaGetSymbolAddress(&p, g_srtB);  srtB  = (int*)p;
    cudaGetSymbolAddress(&p, g_srtBB); srtBB = (int*)p;
    cudaGetSymbolAddress(&p, g_srtF);  srtF  = (int*)p;
    cudaGetSymbolAddress(&p, g_offB);  offB  = (int*)p;
    cudaGetSymbolAddress(&p, g_curB);  curB  = (int*)p;
    cudaGetSymbolAddress(&p, g_offBB); offBB = (int*)p;
    cudaGetSymbolAddress(&p, g_curBB); curBB = (int*)p;
    cudaGetSymbolAddress(&p, g_offF);  offF  = (int*)p;
    cudaGetSymbolAddress(&p, g_curF);  curF  = (int*)p;
    cudaGetSymbolAddress(&p, g_w_hi);  wh    = (__nv_bfloat16*)p;
    cudaGetSymbolAddress(&p, g_w_lo);  wl    = (__nv_bfloat16*)p;

    float* out_u = (float*)d_out;
    float* out_i = (float*)d_out + (size_t)NU * OD;

    // --- degrees + CSR build (edges identical across layers: build once) ---
    launch_zero_i(cntB, NI);
    launch_zero_i(cntBB, NU);
    launch_zero_i(cntF, NU);
    launch_count(dst_buys, cntB, EB);
    launch_count(dst_bought, cntBB, EBB);
    launch_count(dst_follows, cntF, EF);
    launch_scan(cntB, offB, curB, NI);
    launch_scan(cntBB, offBB, curBB, NU);
    launch_scan(cntF, offF, curF, NU);
    launch_fill(src_buys, dst_buys, curB, srtB, EB);
    launch_fill(src_bought, dst_bought, curBB, srtBB, EBB);
    launch_fill(src_follows, dst_follows, curF, srtF, EF);

    // --- weight prep (transposed bf16 hi/lo) ---
    launch_prep(lin_u_W, nullptr,      wh + W_LIN_U,       wl + W_LIN_U,       FU, HD);
    launch_prep(lin_i_W, nullptr,      wh + W_LIN_I,       wl + W_LIN_I,       FI, HD);
    launch_prep(c1_buys_Wl, nullptr,   wh + W_C1_BUYS_L,   wl + W_C1_BUYS_L,   HD, HD);
    launch_prep(c1_bought_Wl, nullptr, wh + W_C1_BOUGHT_L, wl + W_C1_BOUGHT_L, HD, HD);
    launch_prep(c1_follows_Wl, nullptr,wh + W_C1_FOLLOWS_L,wl + W_C1_FOLLOWS_L,HD, HD);
    launch_prep(c1_buys_Wr, nullptr,   wh + W_C1_BUYS_R,   wl + W_C1_BUYS_R,   HD, HD);
    launch_prep(c1_bought_Wr, c1_follows_Wr, wh + W_C1_USER_R, wl + W_C1_USER_R, HD, HD);
    launch_prep(c2_buys_Wl, nullptr,   wh + W_C2_BUYS_L,   wl + W_C2_BUYS_L,   HD, OD);
    launch_prep(c2_bought_Wl, nullptr, wh + W_C2_BOUGHT_L, wl + W_C2_BOUGHT_L, HD, OD);
    launch_prep(c2_follows_Wl, nullptr,wh + W_C2_FOLLOWS_L,wl + W_C2_FOLLOWS_L,HD, OD);
    launch_prep(c2_buys_Wr, nullptr,   wh + W_C2_BUYS_R,   wl + W_C2_BUYS_R,   HD, OD);
    launch_prep(c2_bought_Wr, c2_follows_Wr, wh + W_C2_USER_R, wl + W_C2_USER_R, HD, OD);

    // --- input projections ---
    launch_mma<128>(x_user, wh + W_LIN_U, wl + W_LIN_U, lin_u_b, nullptr,
                    nullptr, nullptr, nullptr, nullptr, hu, NU, FU, 1.f, 0);
    launch_mma<128>(x_item, wh + W_LIN_I, wl + W_LIN_I, lin_i_b, nullptr,
                    nullptr, nullptr, nullptr, nullptr, hi, NI, FI, 1.f, 0);

    // ================= layer 1 (H -> H) =================
    launch_mma<128>(hu, wh + W_C1_BUYS_L, wl + W_C1_BUYS_L, nullptr, nullptr,
                    nullptr, nullptr, nullptr, nullptr, y, NU, HD, 1.f, 0);
    launch_gather<128>(y, offB, cntB, srtB, accI, NI);
    launch_mma<128>(hi, wh + W_C1_BOUGHT_L, wl + W_C1_BOUGHT_L, nullptr, nullptr,
                    nullptr, nullptr, nullptr, nullptr, y, NI, HD, 1.f, 0);
    launch_gather<128>(y, offBB, cntBB, srtBB, accU1, NU);
    launch_mma<128>(hu, wh + W_C1_FOLLOWS_L, wl + W_C1_FOLLOWS_L, nullptr, nullptr,
                    nullptr, nullptr, nullptr, nullptr, y, NU, HD, 1.f, 0);
    launch_gather<128>(y, offF, cntF, srtF, accU2, NU);

    launch_mma<128>(hi, wh + W_C1_BUYS_R, wl + W_C1_BUYS_R, c1_buys_bl, nullptr,
                    accI, cntB, nullptr, nullptr, hi2, NI, HD, 1.f, 1);
    launch_mma<128>(hu, wh + W_C1_USER_R, wl + W_C1_USER_R, c1_bought_bl, c1_follows_bl,
                    accU1, cntBB, accU2, cntF, hu2, NU, HD, 0.5f, 1);

    // ================= layer 2 (H -> O) =================
    launch_mma<64>(hu2, wh + W_C2_BUYS_L, wl + W_C2_BUYS_L, nullptr, nullptr,
                   nullptr, nullptr, nullptr, nullptr, y, NU, HD, 1.f, 0);
    launch_gather<64>(y, offB, cntB, srtB, accI, NI);
    launch_mma<64>(hi2, wh + W_C2_BOUGHT_L, wl + W_C2_BOUGHT_L, nullptr, nullptr,
                   nullptr, nullptr, nullptr, nullptr, y, NI, HD, 1.f, 0);
    launch_gather<64>(y, offBB, cntBB, srtBB, accU1, NU);
    launch_mma<64>(hu2, wh + W_C2_FOLLOWS_L, wl + W_C2_FOLLOWS_L, nullptr, nullptr,
                   nullptr, nullptr, nullptr, nullptr, y, NU, HD, 1.f, 0);
    launch_gather<64>(y, offF, cntF, srtF, accU2, NU);

    launch_mma<64>(hi2, wh + W_C2_BUYS_R, wl + W_C2_BUYS_R, c2_buys_bl, nullptr,
                   accI, cntB, nullptr, nullptr, out_i, NI, HD, 1.f, 0);
    launch_mma<64>(hu2, wh + W_C2_USER_R, wl + W_C2_USER_R, c2_bought_bl, c2_follows_bl,
                   accU1, cntBB, accU2, cntF, out_u, NU, HD, 0.5f, 0);
}

// round 15
// speedup vs baseline: 2.2039x; 1.4165x over previous
#include <cuda_runtime.h>
#include <cuda_bf16.h>
#include <cstdint>

// Problem constants
#define NU 50000
#define NI 25000
#define FU 128
#define FI 64
#define HD 128
#define OD 64
#define EB  400000
#define EBB 400000
#define EF  200000

// ---------------- scratch (static device memory) ----------------------------
__device__ float g_hu  [NU * HD];
__device__ float g_hi  [NI * HD];
__device__ float g_hu2 [NU * HD];
__device__ float g_hi2 [NI * HD];
__device__ float g_yB  [NU * HD];
__device__ float g_yBB [NI * HD];
__device__ float g_yF  [NU * HD];
__device__ float g_accU1[NU * HD];
__device__ float g_accU2[NU * HD];
__device__ float g_accI [NI * HD];
__device__ int   g_cntB [NI];
__device__ int   g_cntBB[NU];
__device__ int   g_cntF [NU];
__device__ int   g_srtB [EB];
__device__ int   g_srtBB[EBB];
__device__ int   g_srtF [EF];
__device__ int   g_offB [NI];
__device__ int   g_curB [NI];
__device__ int   g_offBB[NU];
__device__ int   g_curBB[NU];
__device__ int   g_offF [NU];
__device__ int   g_curF [NU];
__device__ __nv_bfloat16 g_w_hi[147456];
__device__ __nv_bfloat16 g_w_lo[147456];

// weight offsets (elements)
#define W_LIN_U        0
#define W_LIN_I        16384
#define W_C1_BUYS_L    24576
#define W_C1_BOUGHT_L  40960
#define W_C1_FOLLOWS_L 57344
#define W_C1_BUYS_R    73728
#define W_C1_USER_R    90112
#define W_C2_BUYS_L    106496
#define W_C2_BOUGHT_L  114688
#define W_C2_FOLLOWS_L 122880
#define W_C2_BUYS_R    131072
#define W_C2_USER_R    139264

// ---------------- batched setup kernels --------------------------------------
__global__ void zero3_kernel(int* a, int na, int* b, int nb, int* c, int nc) {
    int t = blockIdx.x * blockDim.x + threadIdx.x;
    if (t < na) { a[t] = 0; return; }
    t -= na;
    if (t < nb) { b[t] = 0; return; }
    t -= nb;
    if (t < nc) c[t] = 0;
}
__global__ void count3_kernel(const int* d0, int* c0, int E0,
                              const int* d1, int* c1, int E1,
                              const int* d2, int* c2, int E2) {
    int t = blockIdx.x * blockDim.x + threadIdx.x;
    if (t < E0) { atomicAdd(&c0[d0[t]], 1); return; }
    t -= E0;
    if (t < E1) { atomicAdd(&c1[d1[t]], 1); return; }
    t -= E1;
    if (t < E2) atomicAdd(&c2[d2[t]], 1);
}
__global__ void fill3_kernel(const int* s0, const int* d0, int* u0, int* r0, int E0,
                             const int* s1, const int* d1, int* u1, int* r1, int E1,
                             const int* s2, const int* d2, int* u2, int* r2, int E2) {
    int t = blockIdx.x * blockDim.x + threadIdx.x;
    if (t < E0) { int pos = atomicAdd(&u0[d0[t]], 1); r0[pos] = s0[t]; return; }
    t -= E0;
    if (t < E1) { int pos = atomicAdd(&u1[d1[t]], 1); r1[pos] = s1[t]; return; }
    t -= E1;
    if (t < E2) { int pos = atomicAdd(&u2[d2[t]], 1); r2[pos] = s2[t]; }
}
// 3 exclusive scans, one per block
__global__ void scan3_kernel(const int* c0, int* o0, int* u0, int n0,
                             const int* c1, int* o1, int* u1, int n1,
                             const int* c2, int* o2, int* u2, int n2) {
    const int* cnt; int* off; int* cur; int n;
    if (blockIdx.x == 0)      { cnt = c0; off = o0; cur = u0; n = n0; }
    else if (blockIdx.x == 1) { cnt = c1; off = o1; cur = u1; n = n1; }
    else                      { cnt = c2; off = o2; cur = u2; n = n2; }
    __shared__ int buf[1024];
    __shared__ int carry_s;
    const int tid = threadIdx.x;
    if (tid == 0) carry_s = 0;
    __syncthreads();
    for (int base = 0; base < n; base += 1024) {
        int i = base + tid;
        int v = (i < n) ? cnt[i] : 0;
        buf[tid] = v;
        __syncthreads();
        #pragma unroll
        for (int d = 1; d < 1024; d <<= 1) {
            int t = (tid >= d) ? buf[tid - d] : 0;
            __syncthreads();
            buf[tid] += t;
            __syncthreads();
        }
        int excl = buf[tid] - v;
        if (i < n) { int o = carry_s + excl; off[i] = o; cur[i] = o; }
        __syncthreads();
        if (tid == 1023) carry_s += buf[1023];
        __syncthreads();
    }
}

__device__ __forceinline__ uint16_t bfbits(__nv_bfloat16 h) {
    return *reinterpret_cast<uint16_t*>(&h);
}

// ---------------- batched weight prep ----------------------------------------
struct PrepOp { const float* W1; const float* W2; int off; int K; int N; int t_end; };
struct PrepBatch { PrepOp op[12]; };
__global__ void prep_batch_kernel(PrepBatch B, __nv_bfloat16* __restrict__ hi,
                                  __nv_bfloat16* __restrict__ lo, int total) {
    int t = blockIdx.x * blockDim.x + threadIdx.x;
    if (t >= total) return;
    int oi = 0;
    #pragma unroll
    for (int i = 0; i < 11; ++i) if (t >= B.op[i].t_end) oi = i + 1;
    const PrepOp& O = B.op[oi];
    int lt = t - (oi ? B.op[oi - 1].t_end : 0);
    int n = lt / O.K, k = lt - n * O.K;
    float v = O.W1[k * O.N + n];
    if (O.W2) v += O.W2[k * O.N + n];
    __nv_bfloat16 h = __float2bfloat16_rn(v);
    hi[O.off + lt] = h;
    lo[O.off + lt] = __float2bfloat16_rn(v - __bfloat162float(h));
}

// ---------------- batched gather ---------------------------------------------
struct GatherOp { const float* y; const int* off; const int* cnt; const int* srt;
                  float* acc; int node_end; };
struct GatherBatch { GatherOp op[3]; };
template<int N>
__global__ void gather_batch_kernel(GatherBatch B, int total_warps) {
    int w = (blockIdx.x * blockDim.x + threadIdx.x) >> 5;
    if (w >= total_warps) return;
    int oi = 0;
    #pragma unroll
    for (int i = 0; i < 2; ++i) if (w >= B.op[i].node_end) oi = i + 1;
    const GatherOp& O = B.op[oi];
    const int node = w - (oi ? B.op[oi - 1].node_end : 0);
    const int lane = threadIdx.x & 31;
    const int s = O.off[node];
    const int e = s + O.cnt[node];
    const float* y = O.y;
    const int* srt = O.srt;
    if (N == 128) {
        const int col = lane << 2;
        float4 v0 = make_float4(0.f, 0.f, 0.f, 0.f);
        float4 v1 = make_float4(0.f, 0.f, 0.f, 0.f);
        int i = s;
        for (; i + 1 < e; i += 2) {
            int s0 = srt[i], s1 = srt[i + 1];
            float4 u0 = *reinterpret_cast<const float4*>(&y[(size_t)s0 * 128 + col]);
            float4 u1 = *reinterpret_cast<const float4*>(&y[(size_t)s1 * 128 + col]);
            v0.x += u0.x; v0.y += u0.y; v0.z += u0.z; v0.w += u0.w;
            v1.x += u1.x; v1.y += u1.y; v1.z += u1.z; v1.w += u1.w;
        }
        if (i < e) {
            float4 u = *reinterpret_cast<const float4*>(&y[(size_t)srt[i] * 128 + col]);
            v0.x += u.x; v0.y += u.y; v0.z += u.z; v0.w += u.w;
        }
        v0.x += v1.x; v0.y += v1.y; v0.z += v1.z; v0.w += v1.w;
        *reinterpret_cast<float4*>(&O.acc[(size_t)node * 128 + col]) = v0;
    } else {
        const int col = lane << 1;
        float2 v0 = make_float2(0.f, 0.f);
        float2 v1 = make_float2(0.f, 0.f);
        int i = s;
        for (; i + 1 < e; i += 2) {
            int s0 = srt[i], s1 = srt[i + 1];
            float2 u0 = *reinterpret_cast<const float2*>(&y[(size_t)s0 * 64 + col]);
            float2 u1 = *reinterpret_cast<const float2*>(&y[(size_t)s1 * 64 + col]);
            v0.x += u0.x; v0.y += u0.y;
            v1.x += u1.x; v1.y += u1.y;
        }
        if (i < e) {
            float2 u = *reinterpret_cast<const float2*>(&y[(size_t)srt[i] * 64 + col]);
            v0.x += u.x; v0.y += u.y;
        }
        v0.x += v1.x; v0.y += v1.y;
        *reinterpret_cast<float2*>(&O.acc[(size_t)node * 64 + col]) = v0;
    }
}

// ---------------- mma.sync helpers -------------------------------------------
__device__ __forceinline__ void ldsm_x4(uint32_t r[4], uint32_t saddr) {
    asm volatile("ldmatrix.sync.aligned.m8n8.x4.shared.b16 {%0,%1,%2,%3}, [%4];"
                 : "=r"(r[0]), "=r"(r[1]), "=r"(r[2]), "=r"(r[3]) : "r"(saddr));
}
__device__ __forceinline__ void mma_16816(float c[4], const uint32_t a[4],
                                          uint32_t b0, uint32_t b1) {
    asm volatile(
        "mma.sync.aligned.m16n8k16.row.col.f32.bf16.bf16.f32 "
        "{%0,%1,%2,%3}, {%4,%5,%6,%7}, {%8,%9}, {%0,%1,%2,%3};"
        : "+f"(c[0]), "+f"(c[1]), "+f"(c[2]), "+f"(c[3])
        : "r"(a[0]), "r"(a[1]), "r"(a[2]), "r"(a[3]), "r"(b0), "r"(b1));
}
__device__ __forceinline__ uint32_t smem_addr(const void* p) {
    return (uint32_t)__cvta_generic_to_shared(p);
}
__device__ __forceinline__ uint32_t pack_bf16(float x, float y) {
    __nv_bfloat16 hx = __float2bfloat16_rn(x);
    __nv_bfloat16 hy = __float2bfloat16_rn(y);
    return ((uint32_t)bfbits(hy) << 16) | bfbits(hx);
}

// ---------------- batched bf16x3 HMMA GEMM with fused SAGE epilogue ----------
struct GemmOp {
    const float* A;
    const __nv_bfloat16* Wh;
    const __nv_bfloat16* Wl;
    const float* b1; const float* b2;
    const float* acc1; const int* cnt1;
    const float* acc2; const int* cnt2;
    float* C;
    int M; int K;
    float scale; int relu;
    int tile_end;   // cumulative tile count
};
struct GemmBatch { GemmOp op[3]; };

template<int BN>
__global__ __launch_bounds__(256)
void mma_gemm_batch_kernel(GemmBatch B)
{
    constexpr int LDS = 40;
    constexpr int NATOMS = BN / 16;
    __shared__ __nv_bfloat16 Ah[128 * LDS];
    __shared__ __nv_bfloat16 Al[128 * LDS];
    __shared__ __nv_bfloat16 Bh[BN * LDS];
    __shared__ __nv_bfloat16 Bl[BN * LDS];

    int bt = blockIdx.x;
    int oi = 0;
    #pragma unroll
    for (int i = 0; i < 2; ++i) if (bt >= B.op[i].tile_end) oi = i + 1;
    const GemmOp& O = B.op[oi];
    const int bm = (bt - (oi ? B.op[oi - 1].tile_end : 0)) * 128;
    const float* A = O.A;
    const int M = O.M, K = O.K;

    const int tid  = threadIdx.x;
    const int wid  = tid >> 5;
    const int lane = tid & 31;
    const int mbase = (wid & 3) * 32;
    const int nbase = (wid >> 2) * (BN / 2);

    float acc[2][NATOMS][4];
    #pragma unroll
    for (int i = 0; i < 2; ++i)
        #pragma unroll
        for (int j = 0; j < NATOMS; ++j)
            #pragma unroll
            for (int q = 0; q < 4; ++q) acc[i][j][q] = 0.f;

    for (int k0 = 0; k0 < K; k0 += 32) {
        #pragma unroll
        for (int it = 0; it < 4; ++it) {
            int idx = tid + it * 256;
            int r = idx >> 3;
            int c4 = (idx & 7) << 2;
            int gm = bm + r;
            float4 v = make_float4(0.f, 0.f, 0.f, 0.f);
            if (gm < M)
                v = *reinterpret_cast<const float4*>(&A[(size_t)gm * K + k0 + c4]);
            float hx = __bfloat162float(__float2bfloat16_rn(v.x));
            float hy = __bfloat162float(__float2bfloat16_rn(v.y));
            float hz = __bfloat162float(__float2bfloat16_rn(v.z));
            float hw = __bfloat162float(__float2bfloat16_rn(v.w));
            uint2 hp, lp;
            hp.x = pack_bf16(v.x, v.y);
            hp.y = pack_bf16(v.z, v.w);
            lp.x = pack_bf16(v.x - hx, v.y - hy);
            lp.y = pack_bf16(v.z - hz, v.w - hw);
            *reinterpret_cast<uint2*>(&Ah[r * LDS + c4]) = hp;
            *reinterpret_cast<uint2*>(&Al[r * LDS + c4]) = lp;
        }
        #pragma unroll
        for (int it = 0; it < BN / 32; ++it) {
            int idx = tid + it * 256;
            int n = idx >> 3;
            int c4 = (idx & 7) << 2;
            uint2 hv = *reinterpret_cast<const uint2*>(O.Wh + (size_t)n * K + k0 + c4);
            uint2 lv = *reinterpret_cast<const uint2*>(O.Wl + (size_t)n * K + k0 + c4);
            *reinterpret_cast<uint2*>(&Bh[n * LDS + c4]) = hv;
            *reinterpret_cast<uint2*>(&Bl[n * LDS + c4]) = lv;
        }
        __syncthreads();

        #pragma unroll
        for (int kk = 0; kk < 32; kk += 16) {
            uint32_t ah[2][4], al[2][4];
            const int ar = lane & 15;
            const int ac = kk + ((lane >> 4) << 3);
            #pragma unroll
            for (int i = 0; i < 2; ++i) {
                ldsm_x4(ah[i], smem_addr(&Ah[(mbase + i * 16 + ar) * LDS + ac]));
                ldsm_x4(al[i], smem_addr(&Al[(mbase + i * 16 + ar) * LDS + ac]));
            }
            const int br = (lane & 7) + ((lane >> 4) << 3);
            const int bc = kk + (((lane >> 3) & 1) << 3);
            #pragma unroll
            for (int j2 = 0; j2 < NATOMS / 2; ++j2) {
                uint32_t bh[4], bl[4];
                int n0 = nbase + j2 * 16;
                ldsm_x4(bh, smem_addr(&Bh[(n0 + br) * LDS + bc]));
                ldsm_x4(bl, smem_addr(&Bl[(n0 + br) * LDS + bc]));
                #pragma unroll
                for (int i = 0; i < 2; ++i) {
                    mma_16816(acc[i][2 * j2],     ah[i], bh[0], bh[1]);
                    mma_16816(acc[i][2 * j2 + 1], ah[i], bh[2], bh[3]);
                    mma_16816(acc[i][2 * j2],     ah[i], bl[0], bl[1]);
                    mma_16816(acc[i][2 * j2 + 1], ah[i], bl[2], bl[3]);
                    mma_16816(acc[i][2 * j2],     al[i], bh[0], bh[1]);
                    mma_16816(acc[i][2 * j2 + 1], al[i], bh[2], bh[3]);
                }
            }
        }
        __syncthreads();
    }

    const int qr = lane >> 2;
    const int qc = (lane & 3) << 1;
    #pragma unroll
    for (int i = 0; i < 2; ++i) {
        #pragma unroll
        for (int h = 0; h < 2; ++h) {
            int m = bm + mbase + i * 16 + qr + 8 * h;
            if (m >= M) continue;
            float inv1 = 0.f, inv2 = 0.f;
            if (O.cnt1) { int c = O.cnt1[m]; inv1 = 1.f / (float)(c > 0 ? c : 1); }
            if (O.cnt2) { int c = O.cnt2[m]; inv2 = 1.f / (float)(c > 0 ? c : 1); }
            #pragma unroll
            for (int j = 0; j < NATOMS; ++j) {
                int n = nbase + j * 8 + qc;
                float v0 = acc[i][j][2 * h + 0];
                float v1 = acc[i][j][2 * h + 1];
                if (O.b1) { v0 += O.b1[n]; v1 += O.b1[n + 1]; }
                if (O.b2) { v0 += O.b2[n]; v1 += O.b2[n + 1]; }
                if (O.acc1) {
                    float2 a = *reinterpret_cast<const float2*>(&O.acc1[(size_t)m * BN + n]);
                    v0 += a.x * inv1; v1 += a.y * inv1;
                }
                if (O.acc2) {
                    float2 a = *reinterpret_cast<const float2*>(&O.acc2[(size_t)m * BN + n]);
                    v0 += a.x * inv2; v1 += a.y * inv2;
                }
                v0 *= O.scale; v1 *= O.scale;
                if (O.relu) { v0 = fmaxf(v0, 0.f); v1 = fmaxf(v1, 0.f); }
                float2 o; o.x = v0; o.y = v1;
                *reinterpret_cast<float2*>(&O.C[(size_t)m * BN + n]) = o;
            }
        }
    }
}

// ---------------- host-side helpers ------------------------------------------
static inline GemmOp mkop(const float* A, const __nv_bfloat16* Wh, const __nv_bfloat16* Wl,
                          const float* b1, const float* b2,
                          const float* acc1, const int* cnt1,
                          const float* acc2, const int* cnt2,
                          float* C, int M, int K, float scale, int relu) {
    GemmOp o;
    o.A = A; o.Wh = Wh; o.Wl = Wl; o.b1 = b1; o.b2 = b2;
    o.acc1 = acc1; o.cnt1 = cnt1; o.acc2 = acc2; o.cnt2 = cnt2;
    o.C = C; o.M = M; o.K = K; o.scale = scale; o.relu = relu; o.tile_end = 0;
    return o;
}
template<int BN>
static inline void launch_gemm_batch(GemmOp* ops, int nops) {
    GemmBatch B;
    int tiles = 0;
    for (int i = 0; i < 3; ++i) {
        B.op[i] = ops[i < nops ? i : nops - 1];
        if (i < nops) tiles += (B.op[i].M + 127) / 128;
        B.op[i].tile_end = tiles;   // repeated last op keeps tile_end flat
    }
    mma_gemm_batch_kernel<BN><<<tiles, 256>>>(B);
}
static inline GatherOp mkgop(const float* y, const int* off, const int* cnt,
                             const int* srt, float* acc, int nodes) {
    GatherOp o; o.y = y; o.off = off; o.cnt = cnt; o.srt = srt; o.acc = acc;
    o.node_end = nodes; return o;
}
template<int N>
static inline void launch_gather_batch(GatherOp* ops, int nops) {
    GatherBatch B;
    int nodes = 0;
    for (int i = 0; i < 3; ++i) {
        B.op[i] = ops[i < nops ? i : nops - 1];
        if (i < nops) nodes += ops[i].node_end;
        B.op[i].node_end = nodes;
    }
    int threads = nodes * 32;
    gather_batch_kernel<N><<<(threads + 255) / 256, 256>>>(B, nodes);
}

extern "C" void kernel_launch(void* const* d_in, const int* in_sizes, int n_in,
                              void* d_out, int out_size) {
    (void)in_sizes; (void)n_in; (void)out_size;
    const float* x_user      = (const float*)d_in[0];
    const float* x_item      = (const float*)d_in[1];
    const int*   src_buys    = (const int*)d_in[2];
    const int*   dst_buys    = (const int*)d_in[3];
    const int*   src_bought  = (const int*)d_in[4];
    const int*   dst_bought  = (const int*)d_in[5];
    const int*   src_follows = (const int*)d_in[6];
    const int*   dst_follows = (const int*)d_in[7];
    const float* lin_u_W = (const float*)d_in[8];
    const float* lin_u_b = (const float*)d_in[9];
    const float* lin_i_W = (const float*)d_in[10];
    const float* lin_i_b = (const float*)d_in[11];
    const float* c1_buys_Wl    = (const float*)d_in[12];
    const float* c1_buys_bl    = (const float*)d_in[13];
    const float* c1_buys_Wr    = (const float*)d_in[14];
    const float* c1_bought_Wl  = (const float*)d_in[15];
    const float* c1_bought_bl  = (const float*)d_in[16];
    const float* c1_bought_Wr  = (const float*)d_in[17];
    const float* c1_follows_Wl = (const float*)d_in[18];
    const float* c1_follows_bl = (const float*)d_in[19];
    const float* c1_follows_Wr = (const float*)d_in[20];
    const float* c2_buys_Wl    = (const float*)d_in[21];
    const float* c2_buys_bl    = (const float*)d_in[22];
    const float* c2_buys_Wr    = (const float*)d_in[23];
    const float* c2_bought_Wl  = (const float*)d_in[24];
    const float* c2_bought_bl  = (const float*)d_in[25];
    const float* c2_bought_Wr  = (const float*)d_in[26];
    const float* c2_follows_Wl = (const float*)d_in[27];
    const float* c2_follows_bl = (const float*)d_in[28];
    const float* c2_follows_Wr = (const float*)d_in[29];

    void *p;
    float *hu, *hi, *hu2, *hi2, *yB, *yBB, *yF, *accU1, *accU2, *accI;
    int *cntB, *cntBB, *cntF;
    int *srtB, *srtBB, *srtF, *offB, *curB, *offBB, *curBB, *offF, *curF;
    __nv_bfloat16 *wh, *wl;
    cudaGetSymbolAddress(&p, g_hu);    hu    = (float*)p;
    cudaGetSymbolAddress(&p, g_hi);    hi    = (float*)p;
    cudaGetSymbolAddress(&p, g_hu2);   hu2   = (float*)p;
    cudaGetSymbolAddress(&p, g_hi2);   hi2   = (float*)p;
    cudaGetSymbolAddress(&p, g_yB);    yB    = (float*)p;
    cudaGetSymbolAddress(&p, g_yBB);   yBB   = (float*)p;
    cudaGetSymbolAddress(&p, g_yF);    yF    = (float*)p;
    cudaGetSymbolAddress(&p, g_accU1); accU1 = (float*)p;
    cudaGetSymbolAddress(&p, g_accU2); accU2 = (float*)p;
    cudaGetSymbolAddress(&p, g_accI);  accI  = (float*)p;
    cudaGetSymbolAddress(&p, g_cntB);  cntB  = (int*)p;
    cudaGetSymbolAddress(&p, g_cntBB); cntBB = (int*)p;
    cudaGetSymbolAddress(&p, g_cntF);  cntF  = (int*)p;
    cudaGetSymbolAddress(&p, g_srtB);  srtB  = (int*)p;
    cudaGetSymbolAddress(&p, g_srtBB); srtBB = (int*)p;
    cudaGetSymbolAddress(&p, g_srtF);  srtF  = (int*)p;
    cudaGetSymbolAddress(&p, g_offB);  offB  = (int*)p;
    cudaGetSymbolAddress(&p, g_curB);  curB  = (int*)p;
    cudaGetSymbolAddress(&p, g_offBB); offBB = (int*)p;
    cudaGetSymbolAddress(&p, g_curBB); curBB = (int*)p;
    cudaGetSymbolAddress(&p, g_offF);  offF  = (int*)p;
    cudaGetSymbolAddress(&p, g_curF);  curF  = (int*)p;
    cudaGetSymbolAddress(&p, g_w_hi);  wh    = (__nv_bfloat16*)p;
    cudaGetSymbolAddress(&p, g_w_lo);  wl    = (__nv_bfloat16*)p;

    float* out_u = (float*)d_out;
    float* out_i = (float*)d_out + (size_t)NU * OD;

    // ---- setup: degrees + CSR (4 launches) ----
    {
        int n = NI + NU + NU;
        zero3_kernel<<<(n + 255) / 256, 256>>>(cntB, NI, cntBB, NU, cntF, NU);
    }
    {
        int n = EB + EBB + EF;
        count3_kernel<<<(n + 255) / 256, 256>>>(dst_buys, cntB, EB,
                                                dst_bought, cntBB, EBB,
                                                dst_follows, cntF, EF);
    }
    scan3_kernel<<<3, 1024>>>(cntB, offB, curB, NI,
                              cntBB, offBB, curBB, NU,
                              cntF, offF, curF, NU);
    {
        int n = EB + EBB + EF;
        fill3_kernel<<<(n + 255) / 256, 256>>>(src_buys, dst_buys, curB, srtB, EB,
                                               src_bought, dst_bought, curBB, srtBB, EBB,
                                               src_follows, dst_follows, curF, srtF, EF);
    }

    // ---- all 12 weight preps in ONE launch ----
    {
        PrepBatch B;
        auto mkp = [](const float* W1, const float* W2, int off, int K, int N) {
            PrepOp o; o.W1 = W1; o.W2 = W2; o.off = off; o.K = K; o.N = N; o.t_end = 0;
            return o;
        };
        B.op[0]  = mkp(lin_u_W, nullptr,      W_LIN_U,       FU, HD);
        B.op[1]  = mkp(lin_i_W, nullptr,      W_LIN_I,       FI, HD);
        B.op[2]  = mkp(c1_buys_Wl, nullptr,   W_C1_BUYS_L,   HD, HD);
        B.op[3]  = mkp(c1_bought_Wl, nullptr, W_C1_BOUGHT_L, HD, HD);
        B.op[4]  = mkp(c1_follows_Wl, nullptr,W_C1_FOLLOWS_L,HD, HD);
        B.op[5]  = mkp(c1_buys_Wr, nullptr,   W_C1_BUYS_R,   HD, HD);
        B.op[6]  = mkp(c1_bought_Wr, c1_follows_Wr, W_C1_USER_R, HD, HD);
        B.op[7]  = mkp(c2_buys_Wl, nullptr,   W_C2_BUYS_L,   HD, OD);
        B.op[8]  = mkp(c2_bought_Wl, nullptr, W_C2_BOUGHT_L, HD, OD);
        B.op[9]  = mkp(c2_follows_Wl, nullptr,W_C2_FOLLOWS_L,HD, OD);
        B.op[10] = mkp(c2_buys_Wr, nullptr,   W_C2_BUYS_R,   HD, OD);
        B.op[11] = mkp(c2_bought_Wr, c2_follows_Wr, W_C2_USER_R, HD, OD);
        int total = 0;
        for (int i = 0; i < 12; ++i) { total += B.op[i].K * B.op[i].N; B.op[i].t_end = total; }
        prep_batch_kernel<<<(total + 255) / 256, 256>>>(B, wh, wl, total);
    }

    // ---- input projections (1 launch) ----
    {
        GemmOp ops[2] = {
            mkop(x_user, wh + W_LIN_U, wl + W_LIN_U, lin_u_b, nullptr,
                 nullptr, nullptr, nullptr, nullptr, hu, NU, FU, 1.f, 0),
            mkop(x_item, wh + W_LIN_I, wl + W_LIN_I, lin_i_b, nullptr,
                 nullptr, nullptr, nullptr, nullptr, hi, NI, FI, 1.f, 0) };
        launch_gemm_batch<128>(ops, 2);
    }

    // ---- layer 1: transforms (1), gathers (1), R-GEMMs (1) ----
    {
        GemmOp ops[3] = {
            mkop(hu, wh + W_C1_BUYS_L, wl + W_C1_BUYS_L, nullptr, nullptr,
                 nullptr, nullptr, nullptr, nullptr, yB, NU, HD, 1.f, 0),
            mkop(hi, wh + W_C1_BOUGHT_L, wl + W_C1_BOUGHT_L, nullptr, nullptr,
                 nullptr, nullptr, nullptr, nullptr, yBB, NI, HD, 1.f, 0),
            mkop(hu, wh + W_C1_FOLLOWS_L, wl + W_C1_FOLLOWS_L, nullptr, nullptr,
                 nullptr, nullptr, nullptr, nullptr, yF, NU, HD, 1.f, 0) };
        launch_gemm_batch<128>(ops, 3);
    }
    {
        GatherOp ops[3] = {
            mkgop(yB, offB, cntB, srtB, accI, NI),
            mkgop(yBB, offBB, cntBB, srtBB, accU1, NU),
            mkgop(yF, offF, cntF, srtF, accU2, NU) };
        launch_gather_batch<128>(ops, 3);
    }
    {
        GemmOp ops[2] = {
            mkop(hi, wh + W_C1_BUYS_R, wl + W_C1_BUYS_R, c1_buys_bl, nullptr,
                 accI, cntB, nullptr, nullptr, hi2, NI, HD, 1.f, 1),
            mkop(hu, wh + W_C1_USER_R, wl + W_C1_USER_R, c1_bought_bl, c1_follows_bl,
                 accU1, cntBB, accU2, cntF, hu2, NU, HD, 0.5f, 1) };
        launch_gemm_batch<128>(ops, 2);
    }

    // ---- layer 2: transforms (1), gathers (1), outputs (1) ----
    {
        GemmOp ops[3] = {
            mkop(hu2, wh + W_C2_BUYS_L, wl + W_C2_BUYS_L, nullptr, nullptr,
                 nullptr, nullptr, nullptr, nullptr, yB, NU, HD, 1.f, 0),
            mkop(hi2, wh + W_C2_BOUGHT_L, wl + W_C2_BOUGHT_L, nullptr, nullptr,
                 nullptr, nullptr, nullptr, nullptr, yBB, NI, HD, 1.f, 0),
            mkop(hu2, wh + W_C2_FOLLOWS_L, wl + W_C2_FOLLOWS_L, nullptr, nullptr,
                 nullptr, nullptr, nullptr, nullptr, yF, NU, HD, 1.f, 0) };
        launch_gemm_batch<64>(ops, 3);
    }
    {
        GatherOp ops[3] = {
            mkgop(yB, offB, cntB, srtB, accI, NI),
            mkgop(yBB, offBB, cntBB, srtBB, accU1, NU),
            mkgop(yF, offF, cntF, srtF, accU2, NU) };
        launch_gather_batch<64>(ops, 3);
    }
    {
        GemmOp ops[2] = {
            mkop(hi2, wh + W_C2_BUYS_R, wl + W_C2_BUYS_R, c2_buys_bl, nullptr,
                 accI, cntB, nullptr, nullptr, out_i, NI, HD, 1.f, 0),
            mkop(hu2, wh + W_C2_USER_R, wl + W_C2_USER_R, c2_bought_bl, c2_follows_bl,
                 accU1, cntBB, accU2, cntF, out_u, NU, HD, 0.5f, 0) };
        launch_gemm_batch<64>(ops, 2);
    }
}